// round 15
// baseline (speedup 1.0000x reference)
#include <cuda_runtime.h>
#include <cstdint>

#define TLEN   8192
#define BATCH  128
#define NS     128
#define EMITN  64
#define NT     160      // 4 compute warps + 1 relay warp
#define HALF   4128     // chunk boundary
#define WARM   64       // chunk2 warmup steps
#define OBSBUF 4160

// ---- packed f32x2 helpers (sm_103a) ----
__device__ __forceinline__ void fma2(unsigned long long& d, unsigned long long a, unsigned long long b) {
    asm("fma.rn.f32x2 %0, %1, %2, %0;" : "+l"(d) : "l"(a), "l"(b));
}
__device__ __forceinline__ unsigned long long mul2(unsigned long long a, unsigned long long b) {
    unsigned long long d;
    asm("mul.rn.f32x2 %0, %1, %2;" : "=l"(d) : "l"(a), "l"(b));
    return d;
}
__device__ __forceinline__ unsigned long long padd(unsigned long long a, unsigned long long b) {
    unsigned long long d;
    asm("add.rn.f32x2 %0, %1, %2;" : "=l"(d) : "l"(a), "l"(b));
    return d;
}
__device__ __forceinline__ unsigned long long pk(float lo, float hi) {
    unsigned long long r;
    asm("mov.b64 %0, {%1, %2};" : "=l"(r) : "f"(lo), "f"(hi));
    return r;
}
__device__ __forceinline__ float hsum2(unsigned long long v) {
    float lo, hi;
    asm("mov.b64 {%0, %1}, %2;" : "=f"(lo), "=f"(hi) : "l"(v));
    return lo + hi;
}

__device__ double g_L1[BATCH];
__device__ double g_L2[BATCH];

// iterations t0..t1, ONE __syncthreads() per step.
// Combine at iteration t applies E/scf PREFETCHED during iteration t-1
// (E static; scf = relay write from t-2 -> delay-4 damped pow2 controller).
__device__ __forceinline__ void run_steps(
    int t0, int t1, int tbase, bool isCompute, int w, int lane, int qs,
    const unsigned long long (&Ar)[64],
    const float* __restrict__ Bsh, const unsigned char* __restrict__ obs_sm,
    float (*ubuf)[NS], float (*part)[4][NS], float (*zs1)[8], float* sc_sm,
    float& E_cur, float& Escf_cur, int& Stot, int& eLast)
{
    for (int t = t0; t <= t1; t++) {
        const int pb = (t - 1) & 1, cb = t & 1;
        if (isCompute) {
            // fused combine of v_{t-1}[qs]: only part[pb] is barrier-fresh
            float r01 = part[pb][0][qs] + part[pb][1][qs];
            float r23 = part[pb][2][qs] + part[pb][3][qs];
            float vq = Escf_cur * (r01 + r23);
            ubuf[pb][qs] = vq;
            __syncwarp();

            // prefetch for combine at t+1 (independent; hidden under FMA phase)
            int o = obs_sm[t - tbase];
            float scf = sc_sm[pb];            // relay write from t-1, stable now
            float En = Bsh[o * NS + qs];
            E_cur = En;
            Escf_cur = En * scf;

            // phase 1: own K-quarter (8 broadcast LDS.128), all 128 states
            const ulonglong2* up = (const ulonglong2*)ubuf[pb] + 8 * w;
            ulonglong2 c[8];
            #pragma unroll
            for (int i = 0; i < 8; i++) c[i] = up[i];

            unsigned long long acc[8];         // acc[2j],acc[2j+1] -> state 4*lane+j
            #pragma unroll
            for (int j = 0; j < 4; j++) {
                acc[2 * j]     = mul2(c[0].x, Ar[16 * j]);
                acc[2 * j + 1] = mul2(c[0].y, Ar[16 * j + 1]);
            }
            #pragma unroll
            for (int i = 1; i < 8; i++) {
                #pragma unroll
                for (int j = 0; j < 4; j++) {
                    fma2(acc[2 * j],     c[i].x, Ar[16 * j + 2 * i]);
                    fma2(acc[2 * j + 1], c[i].y, Ar[16 * j + 2 * i + 1]);
                }
            }
            float4 pf;
            pf.x = hsum2(padd(acc[0], acc[1]));
            pf.y = hsum2(padd(acc[2], acc[3]));
            pf.z = hsum2(padd(acc[4], acc[5]));
            pf.w = hsum2(padd(acc[6], acc[7]));
            *(float4*)&part[cb][w][4 * lane] = pf;      // STS.128
        } else {
            // relay: reads v_{t-2} (ubuf[cb]); pipelined sum; damped pow2 (gain 1/4)
            float4 za, zb;
            if (lane == 0) {
                za = *(const float4*)&zs1[pb][0];
                zb = *(const float4*)&zs1[pb][4];
            }
            float4 a = ((const float4*)ubuf[cb])[lane];
            float zsum = (a.x + a.y) + (a.z + a.w);
            zsum += __shfl_xor_sync(0xffffffffu, zsum, 1);
            zsum += __shfl_xor_sync(0xffffffffu, zsum, 2);
            if ((lane & 3) == 0) zs1[cb][lane >> 2] = zsum;
            if (lane == 0) {
                float Z = ((za.x + za.y) + (za.z + za.w)) + ((zb.x + zb.y) + (zb.z + zb.w));
                int e = ((((__float_as_int(Z) >> 23) & 255) - 127) >> 2);
                Stot += e; eLast = e;                   // e_t applied at combine t+2
                sc_sm[cb] = __int_as_float((127 - e) << 23);   // 2^{-e}, exact
            }
        }
        __syncthreads();
    }
}

__global__ __launch_bounds__(NT, 2)
void hmm_chunk_kernel(const float* __restrict__ inputs,
                      const float* __restrict__ Ivec,
                      const float* __restrict__ Amat,
                      const float* __restrict__ Bmat,
                      float* __restrict__ out)
{
    __shared__ float Bsh[EMITN * NS];               // 32 KB
    __shared__ unsigned char obs_sm[OBSBUF];        // 4.1 KB
    __shared__ __align__(16) float ubuf[2][NS];
    __shared__ __align__(16) float part[2][4][NS];  // parity double-buffered partials
    __shared__ __align__(16) float zs1[2][8];
    __shared__ float sc_sm[2];
    __shared__ __align__(16) float znext[4];
    __shared__ __align__(16) float zvs[4];
    __shared__ int stot_sm;
    __shared__ double snapL;

    const int tid  = threadIdx.x;
    const int s    = tid & 127;
    const int w    = tid >> 5;          // compute: K-quarter id (0..3)
    const int lane = tid & 31;
    const int qs   = 32 * (w & 3) + lane;   // == s for compute threads
    const bool isCompute = (tid < 128);

    const int b   = blockIdx.x >> 1;     // batch
    const int cid = blockIdx.x & 1;      // 0 = first half, 1 = second half
    const int tbase  = cid ? (HALF - WARM) : 0;
    const int tcount = cid ? (TLEN - tbase) : (HALF + 1);
    const int t0     = cid ? (HALF - WARM + 1) : 1;

    // ---- prologue: B into smem ----
    for (int i = tid; i < EMITN * NS; i += NT) Bsh[i] = Bmat[i];

    // ---- prologue: one-hot -> obs index, own window only ----
    {
        const float* xin = inputs + (size_t)b * TLEN * EMITN;
        for (int tt = tid; tt < tcount; tt += NT) {
            const float4* r = (const float4*)(xin + (size_t)(tbase + tt) * EMITN);
            float idx = 0.0f;
            #pragma unroll
            for (int j = 0; j < 16; j++) {
                float4 v = r[j];
                idx = fmaf((float)(4 * j + 0), v.x, idx);
                idx = fmaf((float)(4 * j + 1), v.y, idx);
                idx = fmaf((float)(4 * j + 2), v.z, idx);
                idx = fmaf((float)(4 * j + 3), v.w, idx);
            }
            obs_sm[tt] = (unsigned char)__float2int_rn(idx);
        }
    }

    // ---- prologue: A block [32w..32w+32) x {4*lane..4*lane+3} ----
    unsigned long long Ar[64];
    if (isCompute) {
        #pragma unroll
        for (int j = 0; j < 4; j++) {
            const int sj = 4 * lane + j;
            #pragma unroll
            for (int i = 0; i < 8; i++) {
                const int k0 = 32 * w + 4 * i;
                Ar[16 * j + 2 * i]     = pk(Amat[(k0 + 0) * NS + sj], Amat[(k0 + 1) * NS + sj]);
                Ar[16 * j + 2 * i + 1] = pk(Amat[(k0 + 2) * NS + sj], Amat[(k0 + 3) * NS + sj]);
            }
        }
    }
    float Ival = isCompute ? Ivec[s] : 0.0f;
    __syncthreads();

    // ---- seed ----
    const int sb = (t0 - 1) & 1;
    float E_cur = 0.f, Escf_cur = 0.f;
    if (isCompute) {
        part[sb][0][s] = cid ? 0.0078125f : Ival;   // combine at t0 -> E∘I / E∘uniform
        part[sb][1][s] = 0.0f;
        part[sb][2][s] = 0.0f;
        part[sb][3][s] = 0.0f;
        ubuf[t0 & 1][s] = 0.0078125f;               // relay's first read: Z = 1
        int o0 = obs_sm[t0 - 1 - tbase];
        E_cur = Bsh[o0 * NS + qs];
        Escf_cur = E_cur;                           // scf seed = 1.0
    } else {
        if (lane < 8) { zs1[0][lane] = 0.125f; zs1[1][lane] = 0.125f; }
        if (lane == 0) { sc_sm[0] = 1.0f; sc_sm[1] = 1.0f; }
    }
    __syncthreads();

    int Stot = 0, eLast = 0;                        // valid on tid==128

    if (cid == 0) {
        // ======== chunk 1: exact forward, iterations 1..HALF ========
        run_steps(1, HALF, tbase, isCompute, w, lane, qs, Ar, Bsh, obs_sm,
                  ubuf, part, zs1, sc_sm, E_cur, Escf_cur, Stot, eLast);

        if (tid == 128) stot_sm = Stot - eLast;     // only e_HALF unapplied
        __syncthreads();
        if (isCompute) {
            const int fb = HALF & 1;
            float R = (part[fb][0][s] + part[fb][1][s]) + (part[fb][2][s] + part[fb][3][s]);
            float vv = Escf_cur * R;                // carried regs = this combine's E*scf
            #pragma unroll
            for (int off = 16; off > 0; off >>= 1) vv += __shfl_xor_sync(0xffffffffu, vv, off);
            if (lane == 0) zvs[w] = vv;
        }
        __syncthreads();
        if (tid == 0) {
            float4 zv = *(const float4*)zvs;
            float SV = (zv.x + zv.y) + (zv.z + zv.w);
            g_L1[b] = log((double)SV) + (double)stot_sm * 0.6931471805599453;
        }
    } else {
        // ======== chunk 2: warmup iterations t0..HALF ========
        run_steps(t0, HALF, tbase, isCompute, w, lane, qs, Ar, Bsh, obs_sm,
                  ubuf, part, zs1, sc_sm, E_cur, Escf_cur, Stot, eLast);

        // snapshot of v_HALF (preview of the combine the loop redoes at HALF+1)
        if (tid == 128) stot_sm = Stot - eLast;
        __syncthreads();
        if (isCompute) {
            const int fb = HALF & 1;
            float R = (part[fb][0][s] + part[fb][1][s]) + (part[fb][2][s] + part[fb][3][s]);
            float vv = Escf_cur * R;
            #pragma unroll
            for (int off = 16; off > 0; off >>= 1) vv += __shfl_xor_sync(0xffffffffu, vv, off);
            if (lane == 0) zvs[w] = vv;
        }
        __syncthreads();
        if (tid == 0) {
            float4 zv = *(const float4*)zvs;
            float SV = (zv.x + zv.y) + (zv.z + zv.w);
            snapL = log((double)SV) + (double)stot_sm * 0.6931471805599453;
        }
        __syncthreads();

        // ======== chunk 2 main: iterations HALF+1 .. TLEN-1 ========
        // (E_cur/Escf_cur carried across the boundary are exactly what the
        //  combine at HALF+1 needs)
        run_steps(HALF + 1, TLEN - 1, tbase, isCompute, w, lane, qs, Ar, Bsh, obs_sm,
                  ubuf, part, zs1, sc_sm, E_cur, Escf_cur, Stot, eLast);

        if (tid == 128) stot_sm = Stot - eLast;
        __syncthreads();
        float E = 0.f, R = 0.f;
        if (isCompute) {
            const int fb = (TLEN - 1) & 1;
            E = E_cur;
            R = (part[fb][0][s] + part[fb][1][s]) + (part[fb][2][s] + part[fb][3][s]);
            float vv = Escf_cur * R;
            float rr = R;
            #pragma unroll
            for (int off = 16; off > 0; off >>= 1) {
                rr += __shfl_xor_sync(0xffffffffu, rr, off);
                vv += __shfl_xor_sync(0xffffffffu, vv, off);
            }
            if (lane == 0) { znext[w] = rr; zvs[w] = vv; }
        }
        __syncthreads();

        if (isCompute) {
            float4 zn = *(const float4*)znext;
            float SR = (zn.x + zn.y) + (zn.z + zn.w);  // = sum v_{T-2} (A rows sum to 1)
            out[b * NS + s] = E * R / SR;              // alpha_f (pow2+scf cancel)
        }
        if (tid == 0) {
            float4 zv = *(const float4*)zvs;
            float SV = (zv.x + zv.y) + (zv.z + zv.w);  // sum v_{T-1}
            double Lfin = log((double)SV) + (double)stot_sm * 0.6931471805599453;
            g_L2[b] = Lfin - snapL;
        }
    }
}

__global__ void ll_combine_kernel(float* __restrict__ out)
{
    int b = threadIdx.x;
    out[BATCH * NS + b] = (float)(g_L1[b] + g_L2[b]);
}

extern "C" void kernel_launch(void* const* d_in, const int* in_sizes, int n_in,
                              void* d_out, int out_size)
{
    const float* inputs = (const float*)d_in[0];   // [128, 8192, 64]
    const float* Ivec   = (const float*)d_in[1];   // [128]
    const float* Amat   = (const float*)d_in[2];   // [128, 128]
    const float* Bmat   = (const float*)d_in[3];   // [64, 128]
    float* out = (float*)d_out;                    // alpha_f [128,128] ++ loglik [128]

    hmm_chunk_kernel<<<2 * BATCH, NT>>>(inputs, Ivec, Amat, Bmat, out);
    ll_combine_kernel<<<1, BATCH>>>(out);
}

// round 16
// speedup vs baseline: 1.3401x; 1.3401x over previous
#include <cuda_runtime.h>
#include <cstdint>

#define TLEN   8192
#define BATCH  128
#define NS     128
#define EMITN  64
#define NT     128      // 4 compute warps, no relay
#define HALF   4128     // chunk boundary
#define WARM   64       // chunk2 warmup steps
#define OBSBUF 4160

// ---- packed f32x2 helpers (sm_103a) ----
__device__ __forceinline__ void fma2(unsigned long long& d, unsigned long long a, unsigned long long b) {
    asm("fma.rn.f32x2 %0, %1, %2, %0;" : "+l"(d) : "l"(a), "l"(b));
}
__device__ __forceinline__ unsigned long long mul2(unsigned long long a, unsigned long long b) {
    unsigned long long d;
    asm("mul.rn.f32x2 %0, %1, %2;" : "=l"(d) : "l"(a), "l"(b));
    return d;
}
__device__ __forceinline__ unsigned long long padd(unsigned long long a, unsigned long long b) {
    unsigned long long d;
    asm("add.rn.f32x2 %0, %1, %2;" : "=l"(d) : "l"(a), "l"(b));
    return d;
}
__device__ __forceinline__ unsigned long long pk(float lo, float hi) {
    unsigned long long r;
    asm("mov.b64 %0, {%1, %2};" : "=l"(r) : "f"(lo), "f"(hi));
    return r;
}
__device__ __forceinline__ float hsum2(unsigned long long v) {
    float lo, hi;
    asm("mov.b64 {%0, %1}, %2;" : "=f"(lo), "=f"(hi) : "l"(v));
    return lo + hi;
}

__device__ double g_L1[BATCH];
__device__ double g_L2[BATCH];

// iterations t0..t1, ONE __syncthreads() per step.
// Combine at iteration t produces v_{t-1}; tid 0 runs the deadbeat pow2
// controller from its own vq register (e_t applied at combine t+1 -> v_t).
__device__ __forceinline__ void run_steps(
    int t0, int t1, int tbase, int tid, int w, int s,
    const unsigned long long (&Ar)[64],
    const float* __restrict__ Bsh, const unsigned char* __restrict__ obs_sm,
    float (*ubuf)[NS], float (*part)[4][NS], float* sc_sm, int& Stot)
{
    for (int t = t0; t <= t1; t++) {
        const int pb = (t - 1) & 1, cb = t & 1;

        // fused combine of v_{t-1}[s] (loads all issue in parallel post-barrier)
        float scf = sc_sm[pb];
        int o = obs_sm[t - 1 - tbase];
        float Eq = Bsh[o * NS + s];
        float r01 = part[pb][0][s] + part[pb][1][s];
        float r23 = part[pb][2][s] + part[pb][3][s];
        float vq = (Eq * scf) * (r01 + r23);
        ubuf[pb][s] = vq;
        if (tid == 0) {                                   // deadbeat controller
            int e = ((__float_as_int(vq) >> 23) & 255) - 127;
            Stot += e;
            sc_sm[cb] = __int_as_float((127 - e) << 23);  // 2^{-e}, exact
        }
        __syncwarp();

        // FMA phase: own K-quarter (8 broadcast LDS.128), all 128 states
        const ulonglong2* up = (const ulonglong2*)ubuf[pb] + 8 * w;
        ulonglong2 c[8];
        #pragma unroll
        for (int i = 0; i < 8; i++) c[i] = up[i];

        unsigned long long acc[8];            // acc[2j],acc[2j+1] -> state 4*lane+j
        #pragma unroll
        for (int j = 0; j < 4; j++) {
            acc[2 * j]     = mul2(c[0].x, Ar[16 * j]);
            acc[2 * j + 1] = mul2(c[0].y, Ar[16 * j + 1]);
        }
        #pragma unroll
        for (int i = 1; i < 8; i++) {
            #pragma unroll
            for (int j = 0; j < 4; j++) {
                fma2(acc[2 * j],     c[i].x, Ar[16 * j + 2 * i]);
                fma2(acc[2 * j + 1], c[i].y, Ar[16 * j + 2 * i + 1]);
            }
        }
        float4 pf;
        pf.x = hsum2(padd(acc[0], acc[1]));
        pf.y = hsum2(padd(acc[2], acc[3]));
        pf.z = hsum2(padd(acc[4], acc[5]));
        pf.w = hsum2(padd(acc[6], acc[7]));
        *(float4*)&part[cb][w][4 * (s & 31)] = pf;        // STS.128

        __syncthreads();
    }
}

__global__ __launch_bounds__(NT, 2)
void hmm_chunk_kernel(const float* __restrict__ inputs,
                      const float* __restrict__ Ivec,
                      const float* __restrict__ Amat,
                      const float* __restrict__ Bmat,
                      float* __restrict__ out)
{
    __shared__ float Bsh[EMITN * NS];               // 32 KB
    __shared__ unsigned char obs_sm[OBSBUF];        // 4.1 KB
    __shared__ __align__(16) float ubuf[2][NS];
    __shared__ __align__(16) float part[2][4][NS];  // parity double-buffered partials
    __shared__ float sc_sm[2];
    __shared__ __align__(16) float znext[4];
    __shared__ __align__(16) float zvs[4];

    const int tid  = threadIdx.x;
    const int s    = tid;                // state == thread (128 threads)
    const int w    = tid >> 5;           // K-quarter id (0..3)
    const int lane = tid & 31;

    const int b   = blockIdx.x >> 1;     // batch
    const int cid = blockIdx.x & 1;      // 0 = first half, 1 = second half
    const int tbase  = cid ? (HALF - WARM) : 0;
    const int tcount = cid ? (TLEN - tbase) : (HALF + 1);
    const int t0     = cid ? (HALF - WARM + 1) : 1;

    // ---- prologue: B into smem ----
    for (int i = tid; i < EMITN * NS; i += NT) Bsh[i] = Bmat[i];

    // ---- prologue: one-hot -> obs index, own window only ----
    {
        const float* xin = inputs + (size_t)b * TLEN * EMITN;
        for (int tt = tid; tt < tcount; tt += NT) {
            const float4* r = (const float4*)(xin + (size_t)(tbase + tt) * EMITN);
            float idx = 0.0f;
            #pragma unroll
            for (int j = 0; j < 16; j++) {
                float4 v = r[j];
                idx = fmaf((float)(4 * j + 0), v.x, idx);
                idx = fmaf((float)(4 * j + 1), v.y, idx);
                idx = fmaf((float)(4 * j + 2), v.z, idx);
                idx = fmaf((float)(4 * j + 3), v.w, idx);
            }
            obs_sm[tt] = (unsigned char)__float2int_rn(idx);
        }
    }

    // ---- prologue: A block [32w..32w+32) x {4*lane..4*lane+3} ----
    unsigned long long Ar[64];
    {
        #pragma unroll
        for (int j = 0; j < 4; j++) {
            const int sj = 4 * lane + j;
            #pragma unroll
            for (int i = 0; i < 8; i++) {
                const int k0 = 32 * w + 4 * i;
                Ar[16 * j + 2 * i]     = pk(Amat[(k0 + 0) * NS + sj], Amat[(k0 + 1) * NS + sj]);
                Ar[16 * j + 2 * i + 1] = pk(Amat[(k0 + 2) * NS + sj], Amat[(k0 + 3) * NS + sj]);
            }
        }
    }
    float Ival = Ivec[s];
    __syncthreads();

    // ---- seed: combine at t0 must yield E∘I (chunk1) / E∘uniform (chunk2) ----
    const int sb = (t0 - 1) & 1;
    part[sb][0][s] = cid ? 0.0078125f : Ival;
    part[sb][1][s] = 0.0f;
    part[sb][2][s] = 0.0f;
    part[sb][3][s] = 0.0f;
    if (tid == 0) { sc_sm[0] = 1.0f; sc_sm[1] = 1.0f; }
    __syncthreads();

    int Stot = 0;                        // valid on tid==0
    double snapL = 0.0;                  // tid==0 register

    if (cid == 0) {
        // ======== chunk 1: exact forward, iterations 1..HALF ========
        run_steps(1, HALF, tbase, tid, w, s, Ar, Bsh, obs_sm, ubuf, part, sc_sm, Stot);

        // epilogue combine -> v_HALF, reduce, L1  (cumScale = full Stot)
        {
            const int fb = HALF & 1;
            float scf = sc_sm[fb];
            int o = obs_sm[HALF];
            float E = Bsh[o * NS + s];
            float R = (part[fb][0][s] + part[fb][1][s]) + (part[fb][2][s] + part[fb][3][s]);
            float vv = (E * scf) * R;
            #pragma unroll
            for (int off = 16; off > 0; off >>= 1) vv += __shfl_xor_sync(0xffffffffu, vv, off);
            if (lane == 0) zvs[w] = vv;
        }
        __syncthreads();
        if (tid == 0) {
            float4 zv = *(const float4*)zvs;
            float SV = (zv.x + zv.y) + (zv.z + zv.w);
            g_L1[b] = log((double)SV) + (double)Stot * 0.6931471805599453;
        }
    } else {
        // ======== chunk 2: warmup iterations t0..HALF ========
        run_steps(t0, HALF, tbase, tid, w, s, Ar, Bsh, obs_sm, ubuf, part, sc_sm, Stot);

        // snapshot of v_HALF (read-only preview of the combine at HALF+1)
        {
            const int fb = HALF & 1;
            float scf = sc_sm[fb];
            int o = obs_sm[HALF - tbase];
            float E = Bsh[o * NS + s];
            float R = (part[fb][0][s] + part[fb][1][s]) + (part[fb][2][s] + part[fb][3][s]);
            float vv = (E * scf) * R;
            #pragma unroll
            for (int off = 16; off > 0; off >>= 1) vv += __shfl_xor_sync(0xffffffffu, vv, off);
            if (lane == 0) zvs[w] = vv;
        }
        __syncthreads();
        if (tid == 0) {
            float4 zv = *(const float4*)zvs;
            float SV = (zv.x + zv.y) + (zv.z + zv.w);
            snapL = log((double)SV) + (double)Stot * 0.6931471805599453;
        }
        __syncthreads();

        // ======== chunk 2 main: iterations HALF+1 .. TLEN-1 ========
        run_steps(HALF + 1, TLEN - 1, tbase, tid, w, s, Ar, Bsh, obs_sm, ubuf, part, sc_sm, Stot);

        // final epilogue: alpha_f + L2
        float E = 0.f, R = 0.f;
        {
            const int fb = (TLEN - 1) & 1;
            float scf = sc_sm[fb];
            int o = obs_sm[TLEN - 1 - tbase];
            E = Bsh[o * NS + s];
            R = (part[fb][0][s] + part[fb][1][s]) + (part[fb][2][s] + part[fb][3][s]);
            float vv = (E * scf) * R;
            float rr = R;
            #pragma unroll
            for (int off = 16; off > 0; off >>= 1) {
                rr += __shfl_xor_sync(0xffffffffu, rr, off);
                vv += __shfl_xor_sync(0xffffffffu, vv, off);
            }
            if (lane == 0) { znext[w] = rr; zvs[w] = vv; }
        }
        __syncthreads();

        {
            float4 zn = *(const float4*)znext;
            float SR = (zn.x + zn.y) + (zn.z + zn.w);  // = sum v_{T-2} (A rows sum to 1)
            out[b * NS + s] = E * R / SR;              // alpha_f (pow2+scf cancel)
        }
        if (tid == 0) {
            float4 zv = *(const float4*)zvs;
            float SV = (zv.x + zv.y) + (zv.z + zv.w);  // sum v_{T-1}
            double Lfin = log((double)SV) + (double)Stot * 0.6931471805599453;
            g_L2[b] = Lfin - snapL;
        }
    }
}

__global__ void ll_combine_kernel(float* __restrict__ out)
{
    int b = threadIdx.x;
    out[BATCH * NS + b] = (float)(g_L1[b] + g_L2[b]);
}

extern "C" void kernel_launch(void* const* d_in, const int* in_sizes, int n_in,
                              void* d_out, int out_size)
{
    const float* inputs = (const float*)d_in[0];   // [128, 8192, 64]
    const float* Ivec   = (const float*)d_in[1];   // [128]
    const float* Amat   = (const float*)d_in[2];   // [128, 128]
    const float* Bmat   = (const float*)d_in[3];   // [64, 128]
    float* out = (float*)d_out;                    // alpha_f [128,128] ++ loglik [128]

    hmm_chunk_kernel<<<2 * BATCH, NT>>>(inputs, Ivec, Amat, Bmat, out);
    ll_combine_kernel<<<1, BATCH>>>(out);
}